// round 9
// baseline (speedup 1.0000x reference)
#include <cuda_runtime.h>
#include <cstdint>

// Problem constants
#define Bn 4
#define Cn 256
#define Hn 128
#define Wn 224
#define HW (Hn*Wn)
#define PD 4
#define NDISP 9

// Tiling: tile 8x16 outputs, each thread 8 px (one row-half), 9 dy groups
#define TH 8
#define TW 16
#define PX 8
#define CC 4                 // channels per stage
#define NK (Cn / CC)         // 64 stages
#define SROWS (TH + 2*PD)    // 16
#define SREAL (TW + 2*PD)    // 24 real cols
#define SCOLS 28             // padded: conflict-free
#define FCOLS 20             // 16 real + 4 pad
#define NTHREADS 144         // 9 dy x (8 rows x 2 col-halves)

#define S_STAGE (CC * SROWS * SCOLS)   // 1792 floats
#define F_STAGE (CC * TH * FCOLS)      // 640 floats
#define S_BYTES (S_STAGE * 4)
#define F_BYTES (F_STAGE * 4)

#define CSTEP_B (CC * HW * 4)          // gmem byte advance per stage

#define NSLOT_S (CC * SROWS * (SREAL/4))   // 384 16B-chunks for second
#define NSLOT_F (CC * TH * (TW/4))         // 128 chunks for first

typedef unsigned long long ull;

__device__ __forceinline__ uint32_t saddr(const void* p) {
    return (uint32_t)__cvta_generic_to_shared(p);
}
__device__ __forceinline__ void cpa16(uint32_t dst, const float* src, int sz) {
    asm volatile("cp.async.cg.shared.global [%0], [%1], 16, %2;\n"
                 :: "r"(dst), "l"(src), "r"(sz));
}
#define CP_COMMIT() asm volatile("cp.async.commit_group;\n" ::: "memory")
#define CP_WAIT1()  asm volatile("cp.async.wait_group 1;\n" ::: "memory")
#define CP_WAIT0()  asm volatile("cp.async.wait_group 0;\n" ::: "memory")

// (hi word of a, lo word of b) -> packed pair (w_{2k+1}, w_{2k+2})
__device__ __forceinline__ ull mk(ull a, ull b) {
    ull r;
    asm("mov.b64 %0, {%1, %2};" : "=l"(r)
        : "r"((uint32_t)(a >> 32)), "r"((uint32_t)b));
    return r;
}
#define FMA2(a, x, y) asm("fma.rn.f32x2 %0, %1, %2, %0;" : "+l"(a) : "l"(x), "l"(y))
#define UNPACK2(l0, h0, s) asm("mov.b64 {%0, %1}, %2;" : "=f"(l0), "=f"(h0) : "l"(s))

__global__ void __launch_bounds__(NTHREADS, 4)
corr_kernel(const float* __restrict__ first, const float* __restrict__ second,
            float* __restrict__ out)
{
    __shared__ float sS[2 * S_STAGE];
    __shared__ float fS[2 * F_STAGE];

    const int tid = threadIdx.x;
    const int x0g = blockIdx.x * TW;
    const int y0  = blockIdx.y * TH;
    const int b   = blockIdx.z;

    const float* fbase = first  + (size_t)b * Cn * HW;
    const float* sbase = second + (size_t)b * Cn * HW;

    const uint32_t smemS = saddr(sS);
    const uint32_t smemF = saddr(fS);

    // ---- precompute loader slots ONCE (byte offsets, advanced per stage) ----
    // second: 384 chunks over 144 threads -> up to 3 slots each
    uint32_t sgo[3]; uint32_t sso[3]; int ssz[3];
    #pragma unroll
    for (int k = 0; k < 3; k++) {
        int s = tid + k * NTHREADS;
        if (s < NSLOT_S) {
            int c   = s / (SROWS * (SREAL/4));
            int rem = s - c * (SROWS * (SREAL/4));
            int row = rem / (SREAL/4);
            int j   = (rem - row * (SREAL/4)) * 4;
            int gy  = y0 - PD + row;
            int gx  = x0g - PD + j;
            bool ok = ((unsigned)gy < (unsigned)Hn) && ((unsigned)gx < (unsigned)Wn);
            sgo[k] = (uint32_t)(((c * Hn + (ok ? gy : 0)) * Wn + (ok ? gx : 0)) * 4);
            sso[k] = (uint32_t)(((c * SROWS + row) * SCOLS + j) * 4);
            ssz[k] = ok ? 16 : 0;
        } else {
            sgo[k] = 0; sso[k] = 0; ssz[k] = -1;
        }
    }
    // first: 128 chunks (tid < 128)
    uint32_t fgo = 0, fso = 0;
    const bool hasF = (tid < NSLOT_F);
    if (hasF) {
        int c   = tid >> 5;
        int rem = tid & 31;
        int row = rem >> 2;
        int j   = (rem & 3) * 4;
        fgo = (uint32_t)(((c * Hn + (y0 + row)) * Wn + (x0g + j)) * 4);
        fso = (uint32_t)(((c * TH + row) * FCOLS + j) * 4);
    }

    #define ISSUE(buf) do {                                                        \
        uint32_t sb_ = smemS + (buf) * S_BYTES;                                    \
        if (ssz[0] >= 0) { cpa16(sb_ + sso[0], (const float*)((const char*)sbase + sgo[0]), ssz[0]); sgo[0] += CSTEP_B; } \
        if (ssz[1] >= 0) { cpa16(sb_ + sso[1], (const float*)((const char*)sbase + sgo[1]), ssz[1]); sgo[1] += CSTEP_B; } \
        if (ssz[2] >= 0) { cpa16(sb_ + sso[2], (const float*)((const char*)sbase + sgo[2]), ssz[2]); sgo[2] += CSTEP_B; } \
        if (hasF) { cpa16(smemF + (buf) * F_BYTES + fso, (const float*)((const char*)fbase + fgo), 16); fgo += CSTEP_B; } \
        CP_COMMIT();                                                               \
    } while (0)

    // ---- compute mapping: g = dy (uniform per 16-thread half-warp group) ----
    const int g   = tid / 16;            // 0..8 (= dy)
    const int pid = tid & 15;
    const int py  = pid & 7;             // row 0..7
    const int xo  = (pid >> 3) * PX;     // 0 or 8

    // 36 packed accumulators = 72 fp32: [dx][pixel-pair 0..3]
    ull acc[NDISP][4];
    #pragma unroll
    for (int dx = 0; dx < NDISP; dx++)
        #pragma unroll
        for (int p = 0; p < 4; p++) acc[dx][p] = 0ull;

    ISSUE(0);

    const int srow_off = (py + g) * SCOLS + xo;
    const int frow_off = py * FCOLS + xo;

    #pragma unroll 1
    for (int kc = 0; kc < NK; kc++) {
        if (kc + 1 < NK) { ISSUE((kc + 1) & 1); CP_WAIT1(); }
        else             { CP_WAIT0(); }
        __syncthreads();

        const float* sC = sS + (kc & 1) * S_STAGE;
        const float* fC = fS + (kc & 1) * F_STAGE;

        #pragma unroll
        for (int c = 0; c < CC; c++) {
            // first: 8 px -> 4 free pairs
            const ulonglong2 fq0 = *(const ulonglong2*)(fC + c * (TH * FCOLS) + frow_off);
            const ulonglong2 fq1 = *(const ulonglong2*)(fC + c * (TH * FCOLS) + frow_off + 4);
            ull f0 = fq0.x, f1 = fq0.y, f2 = fq1.x, f3 = fq1.y;

            // second window: 16 floats -> 8 free even pairs
            const float* sp = sC + c * (SROWS * SCOLS) + srow_off;
            const ulonglong2 A = *(const ulonglong2*)(sp);
            const ulonglong2 B = *(const ulonglong2*)(sp + 4);
            const ulonglong2 C2 = *(const ulonglong2*)(sp + 8);
            const ulonglong2 D = *(const ulonglong2*)(sp + 12);
            ull q0 = A.x,  q1 = A.y,  q2 = B.x,  q3 = B.y;
            ull q4 = C2.x, q5 = C2.y, q6 = D.x,  q7 = D.y;

            // odd pairs (7 MOVs)
            ull pr[15];
            pr[0]  = q0;            pr[2]  = q1;  pr[4]  = q2;  pr[6]  = q3;
            pr[8]  = q4;            pr[10] = q5;  pr[12] = q6;  pr[14] = q7;
            pr[1]  = mk(q0, q1);    pr[3]  = mk(q1, q2);
            pr[5]  = mk(q2, q3);    pr[7]  = mk(q3, q4);
            pr[9]  = mk(q4, q5);    pr[11] = mk(q5, q6);
            pr[13] = mk(q6, q7);

            #pragma unroll
            for (int dx = 0; dx < NDISP; dx++) {
                FMA2(acc[dx][0], f0, pr[dx]);
                FMA2(acc[dx][1], f1, pr[dx + 2]);
                FMA2(acc[dx][2], f2, pr[dx + 4]);
                FMA2(acc[dx][3], f3, pr[dx + 6]);
            }
        }
        __syncthreads();
    }

    // ---- epilogue: scale and store 8 px per dx ----
    const float inv = 1.0f / (float)Cn;
    #pragma unroll
    for (int dx = 0; dx < NDISP; dx++) {
        float a0, a1, a2, a3, a4, a5, a6, a7;
        UNPACK2(a0, a1, acc[dx][0]);
        UNPACK2(a2, a3, acc[dx][1]);
        UNPACK2(a4, a5, acc[dx][2]);
        UNPACK2(a6, a7, acc[dx][3]);
        int d = g * NDISP + dx;
        float* dst = out + (((size_t)b * (NDISP * NDISP) + d) * HW)
                     + (y0 + py) * Wn + x0g + xo;
        *(float4*)(dst)     = make_float4(a0 * inv, a1 * inv, a2 * inv, a3 * inv);
        *(float4*)(dst + 4) = make_float4(a4 * inv, a5 * inv, a6 * inv, a7 * inv);
    }
}

extern "C" void kernel_launch(void* const* d_in, const int* in_sizes, int n_in,
                              void* d_out, int out_size)
{
    const float* first  = (const float*)d_in[0];
    const float* second = (const float*)d_in[1];
    float* out = (float*)d_out;

    dim3 grid(Wn / TW, Hn / TH, Bn);   // 14 x 16 x 4 = 896 blocks
    corr_kernel<<<grid, NTHREADS>>>(first, second, out);
}

// round 10
// speedup vs baseline: 1.5095x; 1.5095x over previous
#include <cuda_runtime.h>
#include <cstdint>

// Problem constants
#define Bn 4
#define Cn 256
#define Hn 128
#define Wn 224
#define HW (Hn*Wn)
#define PD 4
#define NDISP 9

// Tiling: tile 8x32 outputs, each thread 8 px, 9 dy warps, 1 CTA/SM
#define TH 8
#define TW 32
#define PX 8
#define CC 16                // channels per stage
#define NK (Cn / CC)         // 16 stages
#define SROWS (TH + 2*PD)    // 16
#define SREAL (TW + 2*PD)    // 40 real cols
#define SCOLS 44             // padded: 44*4B=176B row stride -> 11 chunks, 11 mod 8 = 3 (coprime, conflict-free)
#define FCOLS 36             // 32 real + 4 pad: 9 chunks, 1 mod 8 (conflict-free)
#define NTHREADS 288         // 9 dy warps x (8 rows x 4 col-groups of 8 px)

#define S_STAGE (CC * SROWS * SCOLS)   // 11264 floats
#define F_STAGE (CC * TH * FCOLS)      // 4608 floats
#define S_BYTES (S_STAGE * 4)
#define F_BYTES (F_STAGE * 4)
#define SMEM_BYTES (2 * (S_BYTES + F_BYTES))   // 126976 B -> 1 CTA/SM

#define CSTEP_B (CC * HW * 4)          // gmem byte advance per stage

#define SCHUNK_ROW (SREAL/4)               // 10
#define NSLOT_S (CC * SROWS * SCHUNK_ROW)  // 2560 16B-chunks
#define NSLOT_F (CC * TH * (TW/4))         // 1024 chunks
#define KS 9                               // second slots per thread (ceil 2560/288)
#define KF 4                               // first slots per thread (ceil 1024/288)

typedef unsigned long long ull;

__device__ __forceinline__ uint32_t saddr(const void* p) {
    return (uint32_t)__cvta_generic_to_shared(p);
}
__device__ __forceinline__ void cpa16(uint32_t dst, const float* src, int sz) {
    asm volatile("cp.async.cg.shared.global [%0], [%1], 16, %2;\n"
                 :: "r"(dst), "l"(src), "r"(sz));
}
#define CP_COMMIT() asm volatile("cp.async.commit_group;\n" ::: "memory")
#define CP_WAIT0()  asm volatile("cp.async.wait_group 0;\n" ::: "memory")

// (hi word of a, lo word of b) -> packed pair (w_{2k+1}, w_{2k+2})
__device__ __forceinline__ ull mk(ull a, ull b) {
    ull r;
    asm("mov.b64 %0, {%1, %2};" : "=l"(r)
        : "r"((uint32_t)(a >> 32)), "r"((uint32_t)b));
    return r;
}
#define FMA2(a, x, y) asm("fma.rn.f32x2 %0, %1, %2, %0;" : "+l"(a) : "l"(x), "l"(y))
#define UNPACK2(l0, h0, s) asm("mov.b64 {%0, %1}, %2;" : "=f"(l0), "=f"(h0) : "l"(s))

__global__ void __launch_bounds__(NTHREADS, 1)
corr_kernel(const float* __restrict__ first, const float* __restrict__ second,
            float* __restrict__ out)
{
    extern __shared__ float sm[];
    float* sS = sm;                      // [2][CC][SROWS][SCOLS]
    float* fS = sm + 2 * S_STAGE;        // [2][CC][TH][FCOLS]

    const int tid = threadIdx.x;
    const int x0g = blockIdx.x * TW;
    const int y0  = blockIdx.y * TH;
    const int b   = blockIdx.z;

    const float* fbase = first  + (size_t)b * Cn * HW;
    const float* sbase = second + (size_t)b * Cn * HW;

    const uint32_t smemS = saddr(sS);
    const uint32_t smemF = saddr(fS);

    // ---- precompute loader slots ONCE (byte offsets advanced per stage) ----
    uint32_t sgo[KS]; uint32_t sso[KS]; int ssz[KS];
    #pragma unroll
    for (int k = 0; k < KS; k++) {
        int s = tid + k * NTHREADS;
        if (s < NSLOT_S) {
            int c   = s / (SROWS * SCHUNK_ROW);
            int rem = s - c * (SROWS * SCHUNK_ROW);
            int row = rem / SCHUNK_ROW;
            int j   = (rem - row * SCHUNK_ROW) * 4;
            int gy  = y0 - PD + row;
            int gx  = x0g - PD + j;
            bool ok = ((unsigned)gy < (unsigned)Hn) && ((unsigned)gx < (unsigned)Wn);
            sgo[k] = (uint32_t)(((c * Hn + (ok ? gy : 0)) * Wn + (ok ? gx : 0)) * 4);
            sso[k] = (uint32_t)(((c * SROWS + row) * SCOLS + j) * 4);
            ssz[k] = ok ? 16 : 0;
        } else {
            sgo[k] = 0; sso[k] = 0; ssz[k] = -1;
        }
    }
    uint32_t fgo[KF]; uint32_t fso[KF]; int fok[KF];
    #pragma unroll
    for (int k = 0; k < KF; k++) {
        int s = tid + k * NTHREADS;
        if (s < NSLOT_F) {
            int c   = s >> 6;                 // / (8 rows * 8 chunks)
            int rem = s & 63;
            int row = rem >> 3;
            int j   = (rem & 7) * 4;
            fgo[k] = (uint32_t)(((c * Hn + (y0 + row)) * Wn + (x0g + j)) * 4);
            fso[k] = (uint32_t)(((c * TH + row) * FCOLS + j) * 4);
            fok[k] = 1;
        } else {
            fgo[k] = 0; fso[k] = 0; fok[k] = 0;
        }
    }

    #define ISSUE(buf) do {                                                         \
        uint32_t sb_ = smemS + (buf) * S_BYTES;                                     \
        uint32_t fb_ = smemF + (buf) * F_BYTES;                                     \
        _Pragma("unroll")                                                           \
        for (int k = 0; k < KS; k++)                                                \
            if (ssz[k] >= 0) {                                                      \
                cpa16(sb_ + sso[k], (const float*)((const char*)sbase + sgo[k]), ssz[k]); \
                sgo[k] += CSTEP_B;                                                  \
            }                                                                       \
        _Pragma("unroll")                                                           \
        for (int k = 0; k < KF; k++)                                                \
            if (fok[k]) {                                                           \
                cpa16(fb_ + fso[k], (const float*)((const char*)fbase + fgo[k]), 16); \
                fgo[k] += CSTEP_B;                                                  \
            }                                                                       \
        CP_COMMIT();                                                                \
    } while (0)

    // ---- compute mapping: g = dy (warp-uniform) ----
    const int g   = tid >> 5;            // 0..8 (= dy)
    const int pid = tid & 31;
    const int py  = pid & 7;             // row 0..7
    const int xo  = ((pid >> 3) & 3) * PX; // 0,8,16,24

    // 36 packed accumulators = 72 fp32: [dx][pixel-pair 0..3]
    ull acc[NDISP][4];
    #pragma unroll
    for (int dx = 0; dx < NDISP; dx++)
        #pragma unroll
        for (int p = 0; p < 4; p++) acc[dx][p] = 0ull;

    ISSUE(0);

    const int srow_off = (py + g) * SCOLS + xo;
    const int frow_off = py * FCOLS + xo;

    #pragma unroll 1
    for (int kc = 0; kc < NK; kc++) {
        CP_WAIT0();
        __syncthreads();          // all threads done reading buffer ((kc+1)&1) from prior iter
        if (kc + 1 < NK) ISSUE((kc + 1) & 1);   // safe: overwrites only after the sync

        const float* sC = sS + (kc & 1) * S_STAGE;
        const float* fC = fS + (kc & 1) * F_STAGE;

        #pragma unroll
        for (int c = 0; c < CC; c++) {
            // first: 8 px -> 4 free f32x2 pairs
            const float* fp = fC + c * (TH * FCOLS) + frow_off;
            const ulonglong2 fq0 = *(const ulonglong2*)(fp);
            const ulonglong2 fq1 = *(const ulonglong2*)(fp + 4);
            ull f0 = fq0.x, f1 = fq0.y, f2 = fq1.x, f3 = fq1.y;

            // second window: 16 floats -> 8 free even pairs
            const float* sp = sC + c * (SROWS * SCOLS) + srow_off;
            const ulonglong2 A  = *(const ulonglong2*)(sp);
            const ulonglong2 B  = *(const ulonglong2*)(sp + 4);
            const ulonglong2 C2 = *(const ulonglong2*)(sp + 8);
            const ulonglong2 D  = *(const ulonglong2*)(sp + 12);
            ull q0 = A.x,  q1 = A.y,  q2 = B.x,  q3 = B.y;
            ull q4 = C2.x, q5 = C2.y, q6 = D.x,  q7 = D.y;

            // pairs pr[i] = (w_i, w_{i+1}); even free, 7 odd via packs
            ull pr[15];
            pr[0]  = q0;  pr[2]  = q1;  pr[4]  = q2;  pr[6]  = q3;
            pr[8]  = q4;  pr[10] = q5;  pr[12] = q6;  pr[14] = q7;
            pr[1]  = mk(q0, q1);  pr[3]  = mk(q1, q2);
            pr[5]  = mk(q2, q3);  pr[7]  = mk(q3, q4);
            pr[9]  = mk(q4, q5);  pr[11] = mk(q5, q6);
            pr[13] = mk(q6, q7);

            #pragma unroll
            for (int dx = 0; dx < NDISP; dx++) {
                FMA2(acc[dx][0], f0, pr[dx]);
                FMA2(acc[dx][1], f1, pr[dx + 2]);
                FMA2(acc[dx][2], f2, pr[dx + 4]);
                FMA2(acc[dx][3], f3, pr[dx + 6]);
            }
        }
    }

    // ---- epilogue: scale and store 8 px per dx ----
    const float inv = 1.0f / (float)Cn;
    #pragma unroll
    for (int dx = 0; dx < NDISP; dx++) {
        float a0, a1, a2, a3, a4, a5, a6, a7;
        UNPACK2(a0, a1, acc[dx][0]);
        UNPACK2(a2, a3, acc[dx][1]);
        UNPACK2(a4, a5, acc[dx][2]);
        UNPACK2(a6, a7, acc[dx][3]);
        int d = g * NDISP + dx;
        float* dst = out + (((size_t)b * (NDISP * NDISP) + d) * HW)
                     + (y0 + py) * Wn + x0g + xo;
        *(float4*)(dst)     = make_float4(a0 * inv, a1 * inv, a2 * inv, a3 * inv);
        *(float4*)(dst + 4) = make_float4(a4 * inv, a5 * inv, a6 * inv, a7 * inv);
    }
}

extern "C" void kernel_launch(void* const* d_in, const int* in_sizes, int n_in,
                              void* d_out, int out_size)
{
    const float* first  = (const float*)d_in[0];
    const float* second = (const float*)d_in[1];
    float* out = (float*)d_out;

    cudaFuncSetAttribute(corr_kernel, cudaFuncAttributeMaxDynamicSharedMemorySize, SMEM_BYTES);

    dim3 grid(Wn / TW, Hn / TH, Bn);   // 7 x 16 x 4 = 448 blocks
    corr_kernel<<<grid, NTHREADS, SMEM_BYTES>>>(first, second, out);
}